// round 13
// baseline (speedup 1.0000x reference)
#include <cuda_runtime.h>

#define NC 4
#define CS 512
#define NS 256
#define HD 512
#define H  256
#define GAMMA_C 12.0f

#define TIB 8          // i-rows per CTA (1 per warp, 8 warps)
#define TJB 8          // j-rows per CTA (tails staged in smem)

// Scratch: rotated heads, PRE-NEGATED (|h - t| == |t + h'| with h' = -h)
__device__ float g_real[NC * CS * H];
__device__ float g_imag[NC * CS * H];

// ---------------- Kernel A: rotate heads, store negated ----------------
__global__ void rotate_kernel(const float* __restrict__ heads,
                              const float* __restrict__ rel) {
    int i = blockIdx.x;      // 0..2047
    int k = threadIdx.x;     // 0..255
    float re = heads[i * HD + k];
    float im = heads[i * HD + H + k];
    float ph = rel[i * H + k] * 62.8318530717958648f;   // rel * (pi/0.05)
    float s, c;
    __sincosf(ph, &s, &c);
    g_real[i * H + k] = -(re * c - im * s);
    g_imag[i * H + k] = -(re * s + im * c);
}

// ---------------- f32x2 helpers ----------------
__device__ __forceinline__ unsigned long long addx2(unsigned long long a, unsigned long long b) {
    unsigned long long d;
    asm("add.rn.f32x2 %0, %1, %2;" : "=l"(d) : "l"(a), "l"(b));
    return d;
}
__device__ __forceinline__ unsigned long long mulx2(unsigned long long a, unsigned long long b) {
    unsigned long long d;
    asm("mul.rn.f32x2 %0, %1, %2;" : "=l"(d) : "l"(a), "l"(b));
    return d;
}
__device__ __forceinline__ unsigned long long fmax2(unsigned long long a, unsigned long long b, unsigned long long c) {
    unsigned long long d;
    asm("fma.rn.f32x2 %0, %1, %2, %3;" : "=l"(d) : "l"(a), "l"(b), "l"(c));
    return d;
}
__device__ __forceinline__ float sqrt_fast(float x) {
    float y;
    asm("sqrt.approx.f32 %0, %1;" : "=f"(y) : "f"(x));
    return y;
}

// |t + h'| for packed k-pair (h' pre-negated)
__device__ __forceinline__ void accum_pair(unsigned long long hr, unsigned long long hm,
                                           unsigned long long tr, unsigned long long ti,
                                           float& acc) {
    unsigned long long dr = addx2(hr, tr);
    unsigned long long di = addx2(hm, ti);
    unsigned long long s2 = mulx2(dr, dr);
    s2 = fmax2(di, di, s2);
    float lo, hi;
    asm("mov.b64 {%0, %1}, %2;" : "=f"(lo), "=f"(hi) : "l"(s2));
    acc += sqrt_fast(lo);
    acc += sqrt_fast(hi);
}

// ---------------- Kernel B: 1 head row per warp, 5 CTAs/SM ----------------
__global__ __launch_bounds__(256, 5) void score_kernel(const float* __restrict__ tails,
                                                       float* __restrict__ out) {
    // tails tile: TJB j-rows x 512 floats (re 0..255, im 256..511)
    __shared__ __align__(16) float ts[TJB * HD];

    const int tid  = threadIdx.x;
    const int lane = tid & 31;
    const int w    = tid >> 5;        // warp 0..7

    const int c  = blockIdx.z;
    const int bi = blockIdx.x;        // 0..63  (512/8)
    const int bj = blockIdx.y;        // 0..31  (256/8)

    // ---- stage tails (pure copy): 1024 float4, 4 per thread ----
    {
        const float4* src = reinterpret_cast<const float4*>(tails + (size_t)(c * NS + bj * TJB) * HD);
        float4* dst = reinterpret_cast<float4*>(ts);
        #pragma unroll
        for (int it = 0; it < (TJB * HD / 4) / 256; it++)
            dst[tid + it * 256] = src[tid + it * 256];
    }

    // ---- load this warp's single (negated) head row: 4x LDG.128 ----
    const int i0 = c * CS + bi * TIB + w;
    ulonglong2 hr[2], hi[2];
    {
        const ulonglong2* rr = reinterpret_cast<const ulonglong2*>(&g_real[(size_t)i0 * H]);
        const ulonglong2* ri = reinterpret_cast<const ulonglong2*>(&g_imag[(size_t)i0 * H]);
        #pragma unroll
        for (int m = 0; m < 2; m++) {
            int off = lane + 32 * m;          // ull2 index: k-pairs 2*off, 2*off+1
            hr[m] = rr[off];
            hi[m] = ri[off];
        }
    }

    __syncthreads();

    float* orow = out + (size_t)i0 * NS + bj * TJB;

    #pragma unroll 2
    for (int j = 0; j < TJB; j += 2) {
        const ulonglong2* trA = reinterpret_cast<const ulonglong2*>(&ts[j * HD]);
        const ulonglong2* tiA = reinterpret_cast<const ulonglong2*>(&ts[j * HD + H]);
        const ulonglong2* trB = reinterpret_cast<const ulonglong2*>(&ts[(j + 1) * HD]);
        const ulonglong2* tiB = reinterpret_cast<const ulonglong2*>(&ts[(j + 1) * HD + H]);

        float a = 0.f;     // j
        float b = 0.f;     // j+1
        #pragma unroll
        for (int m = 0; m < 2; m++) {
            int off = lane + 32 * m;
            ulonglong2 tAr = trA[off];          // LDS.128, linear phases, conflict-free
            ulonglong2 tAi = tiA[off];
            ulonglong2 tBr = trB[off];
            ulonglong2 tBi = tiB[off];
            accum_pair(hr[m].x, hi[m].x, tAr.x, tAi.x, a);
            accum_pair(hr[m].y, hi[m].y, tAr.y, tAi.y, a);
            accum_pair(hr[m].x, hi[m].x, tBr.x, tBi.x, b);
            accum_pair(hr[m].y, hi[m].y, tBr.y, tBi.y, b);
        }

        // ---- merged 2-way butterfly: j on lane 0, j+1 on lane 16 ----
        a += __shfl_xor_sync(0xFFFFFFFFu, a, 16);
        b += __shfl_xor_sync(0xFFFFFFFFu, b, 16);
        float m0 = (lane < 16) ? a : b;
        m0 += __shfl_xor_sync(0xFFFFFFFFu, m0, 8);
        m0 += __shfl_xor_sync(0xFFFFFFFFu, m0, 4);
        m0 += __shfl_xor_sync(0xFFFFFFFFu, m0, 2);
        m0 += __shfl_xor_sync(0xFFFFFFFFu, m0, 1);

        if ((lane & 15) == 0)
            orow[j + (lane >> 4)] = GAMMA_C - m0;
    }
}

extern "C" void kernel_launch(void* const* d_in, const int* in_sizes, int n_in,
                              void* d_out, int out_size) {
    const float* heads = (const float*)d_in[0];
    const float* rel   = (const float*)d_in[1];
    const float* tails = (const float*)d_in[2];
    float* out = (float*)d_out;

    rotate_kernel<<<NC * CS, H>>>(heads, rel);
    dim3 grid(CS / TIB, NS / TJB, NC);   // (64, 32, 4) = 8192 CTAs
    score_kernel<<<grid, 256>>>(tails, out);
}

// round 14
// speedup vs baseline: 1.2017x; 1.2017x over previous
#include <cuda_runtime.h>

#define NC 4
#define CS 512
#define NS 256
#define HD 512
#define H  256
#define GAMMA_C 12.0f

#define TIB 16         // i-rows per CTA (2 per warp, 8 warps)
#define TJB 8          // j-rows per CTA (tails staged in smem)

// Scratch: rotated heads, PRE-NEGATED (|h - t| == |t + h'| with h' = -h)
__device__ float g_real[NC * CS * H];
__device__ float g_imag[NC * CS * H];

// ---------------- Kernel A: rotate heads, store negated ----------------
__global__ void rotate_kernel(const float* __restrict__ heads,
                              const float* __restrict__ rel) {
    int i = blockIdx.x;      // 0..2047
    int k = threadIdx.x;     // 0..255
    float re = heads[i * HD + k];
    float im = heads[i * HD + H + k];
    float ph = rel[i * H + k] * 62.8318530717958648f;   // rel * (pi/0.05)
    float s, c;
    __sincosf(ph, &s, &c);
    g_real[i * H + k] = -(re * c - im * s);
    g_imag[i * H + k] = -(re * s + im * c);
}

// ---------------- f32x2 helpers ----------------
__device__ __forceinline__ unsigned long long addx2(unsigned long long a, unsigned long long b) {
    unsigned long long d;
    asm("add.rn.f32x2 %0, %1, %2;" : "=l"(d) : "l"(a), "l"(b));
    return d;
}
__device__ __forceinline__ unsigned long long mulx2(unsigned long long a, unsigned long long b) {
    unsigned long long d;
    asm("mul.rn.f32x2 %0, %1, %2;" : "=l"(d) : "l"(a), "l"(b));
    return d;
}
__device__ __forceinline__ unsigned long long fmax2(unsigned long long a, unsigned long long b, unsigned long long c) {
    unsigned long long d;
    asm("fma.rn.f32x2 %0, %1, %2, %3;" : "=l"(d) : "l"(a), "l"(b), "l"(c));
    return d;
}
__device__ __forceinline__ float sqrt_fast(float x) {
    float y;
    asm("sqrt.approx.f32 %0, %1;" : "=f"(y) : "f"(x));
    return y;
}

// |t + h'| for packed k-pair (h' pre-negated); split lo/hi accumulators
__device__ __forceinline__ void accum_pair(unsigned long long hr, unsigned long long hm,
                                           unsigned long long tr, unsigned long long ti,
                                           float& accL, float& accH) {
    unsigned long long dr = addx2(hr, tr);
    unsigned long long di = addx2(hm, ti);
    unsigned long long s2 = mulx2(dr, dr);
    s2 = fmax2(di, di, s2);
    float lo, hi;
    asm("mov.b64 {%0, %1}, %2;" : "=f"(lo), "=f"(hi) : "l"(s2));
    accL += sqrt_fast(lo);
    accH += sqrt_fast(hi);
}

// ---------------- Kernel B: lanes span k; heads in registers; 128-bit loads ----------------
__global__ __launch_bounds__(256, 4) void score_kernel(const float* __restrict__ tails,
                                                       float* __restrict__ out) {
    // tails tile: TJB j-rows x 512 floats (re 0..255, im 256..511)
    __shared__ __align__(16) float ts[TJB * HD];

    const int tid  = threadIdx.x;
    const int lane = tid & 31;
    const int w    = tid >> 5;        // warp 0..7

    const int c  = blockIdx.z;
    const int bi = blockIdx.x;        // 0..31  (512/16)
    const int bj = blockIdx.y;        // 0..31  (256/8)

    // ---- stage tails (pure copy): 1024 float4, 4 per thread ----
    {
        const float4* src = reinterpret_cast<const float4*>(tails + (size_t)(c * NS + bj * TJB) * HD);
        float4* dst = reinterpret_cast<float4*>(ts);
        #pragma unroll
        for (int it = 0; it < (TJB * HD / 4) / 256; it++)
            dst[tid + it * 256] = src[tid + it * 256];
    }

    // ---- load this warp's two (negated) head rows into registers: 8x LDG.128 ----
    const int i0 = c * CS + bi * TIB + 2 * w;
    ulonglong2 hr0[2], hi0[2], hr1[2], hi1[2];
    {
        const ulonglong2* r0r = reinterpret_cast<const ulonglong2*>(&g_real[(size_t)i0 * H]);
        const ulonglong2* r0i = reinterpret_cast<const ulonglong2*>(&g_imag[(size_t)i0 * H]);
        const ulonglong2* r1r = reinterpret_cast<const ulonglong2*>(&g_real[(size_t)(i0 + 1) * H]);
        const ulonglong2* r1i = reinterpret_cast<const ulonglong2*>(&g_imag[(size_t)(i0 + 1) * H]);
        #pragma unroll
        for (int m = 0; m < 2; m++) {
            int off = lane + 32 * m;          // ull2 index: k-pairs 2*off, 2*off+1
            hr0[m] = r0r[off];
            hi0[m] = r0i[off];
            hr1[m] = r1r[off];
            hi1[m] = r1i[off];
        }
    }

    __syncthreads();

    const int gj0 = bj * TJB;
    float* orow0 = out + (size_t)(i0)     * NS + gj0;
    float* orow1 = out + (size_t)(i0 + 1) * NS + gj0;

    #pragma unroll
    for (int j = 0; j < TJB; j += 2) {
        const ulonglong2* trA = reinterpret_cast<const ulonglong2*>(&ts[j * HD]);
        const ulonglong2* tiA = reinterpret_cast<const ulonglong2*>(&ts[j * HD + H]);
        const ulonglong2* trB = reinterpret_cast<const ulonglong2*>(&ts[(j + 1) * HD]);
        const ulonglong2* tiB = reinterpret_cast<const ulonglong2*>(&ts[(j + 1) * HD + H]);

        float a0L = 0.f, a0H = 0.f, a1L = 0.f, a1H = 0.f;   // j   : rows 0,1 (lo/hi split)
        float b0L = 0.f, b0H = 0.f, b1L = 0.f, b1H = 0.f;   // j+1 : rows 0,1
        #pragma unroll
        for (int m = 0; m < 2; m++) {
            int off = lane + 32 * m;
            ulonglong2 tAr = trA[off];          // LDS.128, linear phases, conflict-free
            ulonglong2 tAi = tiA[off];
            ulonglong2 tBr = trB[off];
            ulonglong2 tBi = tiB[off];
            accum_pair(hr0[m].x, hi0[m].x, tAr.x, tAi.x, a0L, a0H);
            accum_pair(hr0[m].y, hi0[m].y, tAr.y, tAi.y, a0L, a0H);
            accum_pair(hr1[m].x, hi1[m].x, tAr.x, tAi.x, a1L, a1H);
            accum_pair(hr1[m].y, hi1[m].y, tAr.y, tAi.y, a1L, a1H);
            accum_pair(hr0[m].x, hi0[m].x, tBr.x, tBi.x, b0L, b0H);
            accum_pair(hr0[m].y, hi0[m].y, tBr.y, tBi.y, b0L, b0H);
            accum_pair(hr1[m].x, hi1[m].x, tBr.x, tBi.x, b1L, b1H);
            accum_pair(hr1[m].y, hi1[m].y, tBr.y, tBi.y, b1L, b1H);
        }

        float a0 = a0L + a0H;
        float a1 = a1L + a1H;
        float b0 = b0L + b0H;
        float b1 = b1L + b1H;

        // ---- merged 4-way butterfly: outputs on lanes 0, 8, 16, 24 ----
        a0 += __shfl_xor_sync(0xFFFFFFFFu, a0, 16);
        a1 += __shfl_xor_sync(0xFFFFFFFFu, a1, 16);
        b0 += __shfl_xor_sync(0xFFFFFFFFu, b0, 16);
        b1 += __shfl_xor_sync(0xFFFFFFFFu, b1, 16);
        float m0 = (lane < 16) ? a0 : b0;
        float m1 = (lane < 16) ? a1 : b1;
        m0 += __shfl_xor_sync(0xFFFFFFFFu, m0, 8);
        m1 += __shfl_xor_sync(0xFFFFFFFFu, m1, 8);
        float n = ((lane & 8) == 0) ? m0 : m1;
        n += __shfl_xor_sync(0xFFFFFFFFu, n, 4);
        n += __shfl_xor_sync(0xFFFFFFFFu, n, 2);
        n += __shfl_xor_sync(0xFFFFFFFFu, n, 1);

        if ((lane & 7) == 0) {
            int idx = lane >> 3;                       // (row0,j) (row1,j) (row0,j+1) (row1,j+1)
            float* p = (idx & 1) ? orow1 : orow0;
            p[j + (idx >> 1)] = GAMMA_C - n;
        }
    }
}

extern "C" void kernel_launch(void* const* d_in, const int* in_sizes, int n_in,
                              void* d_out, int out_size) {
    const float* heads = (const float*)d_in[0];
    const float* rel   = (const float*)d_in[1];
    const float* tails = (const float*)d_in[2];
    float* out = (float*)d_out;

    rotate_kernel<<<NC * CS, H>>>(heads, rel);
    dim3 grid(CS / TIB, NS / TJB, NC);   // (32, 32, 4) = 4096 CTAs
    score_kernel<<<grid, 256>>>(tails, out);
}